// round 1
// baseline (speedup 1.0000x reference)
#include <cuda_runtime.h>
#include <cuda_bf16.h>

#define NN 50000
#define NE 600000
#define D  128
#define NUM_LAYER 5
#define BN_EPS 1e-5f
#define STATS_BLOCKS 512

// ---------------- scratch (static device globals; no allocation) ----------------
__device__ float g_h  [NN * D];     // node features (input to each layer)
__device__ float g_agg[NN * D];     // aggregated messages
__device__ float g_t  [NN * 256];   // hidden after Linear1+ReLU
__device__ float g_h2 [NN * D];     // after Linear2 (pre-BN)
__device__ int   g_deg[NN];
__device__ int   g_off[NN + 1];
__device__ int   g_cur[NN];
__device__ int   g_src [NE];        // CSR-ordered source node ids
__device__ int   g_code[NE];        // CSR-ordered fused edge-attr code (a0*4+a1)
__device__ float g_p1[STATS_BLOCKS * D];
__device__ float g_p2[STATS_BLOCKS * D];
__device__ float g_scale[D];
__device__ float g_shift[D];

// ---------------- kernels ----------------

// h0[n] = atom_emb[x0] + chir_emb[x1] + hyb_emb[x2]   (float4 per thread)
__global__ void k_embed(const int* __restrict__ x,
                        const float* __restrict__ ae,
                        const float* __restrict__ ce,
                        const float* __restrict__ he) {
    int idx = blockIdx.x * blockDim.x + threadIdx.x;       // over NN*32
    if (idx >= NN * 32) return;
    int n  = idx >> 5;
    int c4 = (idx & 31) * 4;
    int x0 = x[n * 3 + 0], x1 = x[n * 3 + 1], x2 = x[n * 3 + 2];
    float4 a = *(const float4*)&ae[x0 * D + c4];
    float4 b = *(const float4*)&ce[x1 * D + c4];
    float4 c = *(const float4*)&he[x2 * D + c4];
    float4 o;
    o.x = a.x + b.x + c.x; o.y = a.y + b.y + c.y;
    o.z = a.z + b.z + c.z; o.w = a.w + b.w + c.w;
    *(float4*)&g_h[n * D + c4] = o;
}

__global__ void k_zero_deg() {
    int i = blockIdx.x * blockDim.x + threadIdx.x;
    if (i < NN) g_deg[i] = 0;
}

__global__ void k_count(const int* __restrict__ ei) {
    int e = blockIdx.x * blockDim.x + threadIdx.x;
    if (e < NE) atomicAdd(&g_deg[ei[NE + e]], 1);
}

// single-block exclusive scan of g_deg -> g_off  (N+1 entries)
__global__ void k_scan() {
    __shared__ int sh[1024];
    __shared__ int carry;
    int tid = threadIdx.x;
    if (tid == 0) carry = 0;
    __syncthreads();
    for (int base = 0; base < NN; base += 1024) {
        int v = (base + tid < NN) ? g_deg[base + tid] : 0;
        sh[tid] = v;
        __syncthreads();
        for (int off = 1; off < 1024; off <<= 1) {
            int t = (tid >= off) ? sh[tid - off] : 0;
            __syncthreads();
            sh[tid] += t;
            __syncthreads();
        }
        if (base + tid < NN) g_off[base + tid] = carry + sh[tid] - v;
        __syncthreads();
        if (tid == 1023) carry += sh[1023];
        __syncthreads();
    }
    if (tid == 0) g_off[NN] = carry;
}

__global__ void k_cur() {
    int i = blockIdx.x * blockDim.x + threadIdx.x;
    if (i < NN) g_cur[i] = g_off[i];
}

__global__ void k_fill(const int* __restrict__ ei, const int* __restrict__ ea) {
    int e = blockIdx.x * blockDim.x + threadIdx.x;
    if (e >= NE) return;
    int d = ei[NE + e];
    int p = atomicAdd(&g_cur[d], 1);
    g_src[p]  = ei[e];
    g_code[p] = ea[2 * e] * 4 + ea[2 * e + 1];
}

// warp-per-node aggregation: agg[n] = sum_{e in-edges} (h[src(e)] + ee[code(e)])
__global__ void k_agg(const float* __restrict__ e1l, const float* __restrict__ e2l) {
    __shared__ __align__(16) float see[24 * D];   // fused edge-emb table (12 KB)
    for (int i = threadIdx.x; i < 24 * D; i += 256) {
        int c = i >> 7, k = i & 127;
        see[i] = e1l[(c >> 2) * D + k] + e2l[(c & 3) * D + k];
    }
    __syncthreads();
    int warp = threadIdx.x >> 5;
    int lane = threadIdx.x & 31;
    int n = blockIdx.x * 8 + warp;
    if (n >= NN) return;
    float4 acc = make_float4(0.f, 0.f, 0.f, 0.f);
    int b = g_off[n], e = g_off[n + 1];
    int c4 = lane * 4;
    for (int j = b; j < e; j++) {
        int s = g_src[j];
        int c = g_code[j];
        float4 hv = *(const float4*)&g_h[s * D + c4];
        float4 ev = *(const float4*)&see[c * D + c4];
        acc.x += hv.x + ev.x; acc.y += hv.y + ev.y;
        acc.z += hv.z + ev.z; acc.w += hv.w + ev.w;
    }
    *(float4*)&g_agg[n * D + c4] = acc;
}

// generic fp32 SIMT GEMM:  C[M,NC] = A[M,K] * B[K,NC] + bias, optional ReLU
// BM=64, BN=64, BK=32, 256 threads, 4x4 micro-tile per thread
__global__ void k_gemm(const float* __restrict__ A, const float* __restrict__ B,
                       const float* __restrict__ bias, float* __restrict__ C,
                       int M, int K, int NC, int relu) {
    __shared__ __align__(16) float As[32][65];   // [k][m], padded
    __shared__ __align__(16) float Bs[32][64];   // [k][n]
    int tid = threadIdx.x;
    int m0 = blockIdx.x * 64;
    int n0 = blockIdx.y * 64;
    int ty = tid >> 4, tx = tid & 15;

    float acc[4][4];
#pragma unroll
    for (int i = 0; i < 4; i++)
#pragma unroll
        for (int j = 0; j < 4; j++) acc[i][j] = 0.f;

    int ar  = tid >> 3;            // 0..31 (two passes: ar, ar+32)
    int ac4 = (tid & 7) * 4;       // 0..28
    int br  = tid >> 4;            // 0..15 (two passes)
    int bc4 = (tid & 15) * 4;

    for (int kb = 0; kb < K; kb += 32) {
        // load A tile (64 x 32), store transposed
#pragma unroll
        for (int p = 0; p < 2; p++) {
            int r = ar + p * 32;
            int gr = m0 + r;
            float4 v = make_float4(0.f, 0.f, 0.f, 0.f);
            if (gr < M) v = *(const float4*)&A[(long)gr * K + kb + ac4];
            As[ac4 + 0][r] = v.x;
            As[ac4 + 1][r] = v.y;
            As[ac4 + 2][r] = v.z;
            As[ac4 + 3][r] = v.w;
        }
        // load B tile (32 x 64)
#pragma unroll
        for (int p = 0; p < 2; p++) {
            int r = br + p * 16;
            float4 v = *(const float4*)&B[(long)(kb + r) * NC + n0 + bc4];
            *(float4*)&Bs[r][bc4] = v;
        }
        __syncthreads();
#pragma unroll
        for (int kk = 0; kk < 32; kk++) {
            float a0 = As[kk][ty * 4 + 0];
            float a1 = As[kk][ty * 4 + 1];
            float a2 = As[kk][ty * 4 + 2];
            float a3 = As[kk][ty * 4 + 3];
            float4 b4 = *(const float4*)&Bs[kk][tx * 4];
            acc[0][0] += a0 * b4.x; acc[0][1] += a0 * b4.y; acc[0][2] += a0 * b4.z; acc[0][3] += a0 * b4.w;
            acc[1][0] += a1 * b4.x; acc[1][1] += a1 * b4.y; acc[1][2] += a1 * b4.z; acc[1][3] += a1 * b4.w;
            acc[2][0] += a2 * b4.x; acc[2][1] += a2 * b4.y; acc[2][2] += a2 * b4.z; acc[2][3] += a2 * b4.w;
            acc[3][0] += a3 * b4.x; acc[3][1] += a3 * b4.y; acc[3][2] += a3 * b4.z; acc[3][3] += a3 * b4.w;
        }
        __syncthreads();
    }

    // epilogue
    float bb[4];
#pragma unroll
    for (int j = 0; j < 4; j++) bb[j] = bias[n0 + tx * 4 + j];
#pragma unroll
    for (int i = 0; i < 4; i++) {
        int gr = m0 + ty * 4 + i;
        if (gr >= M) continue;
        float4 o;
        float v0 = acc[i][0] + bb[0];
        float v1 = acc[i][1] + bb[1];
        float v2 = acc[i][2] + bb[2];
        float v3 = acc[i][3] + bb[3];
        if (relu) {
            v0 = fmaxf(v0, 0.f); v1 = fmaxf(v1, 0.f);
            v2 = fmaxf(v2, 0.f); v3 = fmaxf(v3, 0.f);
        }
        o.x = v0; o.y = v1; o.z = v2; o.w = v3;
        *(float4*)&C[(long)gr * NC + n0 + tx * 4] = o;
    }
}

// deterministic column partial sums of g_h2 (sum, sumsq)
__global__ void k_colstats() {
    int col = threadIdx.x;                 // 128 threads
    float s1 = 0.f, s2 = 0.f;
    for (int r = blockIdx.x; r < NN; r += STATS_BLOCKS) {
        float v = g_h2[r * D + col];
        s1 += v;
        s2 += v * v;
    }
    g_p1[blockIdx.x * D + col] = s1;
    g_p2[blockIdx.x * D + col] = s2;
}

__global__ void k_bnfinal(const float* __restrict__ gamma,
                          const float* __restrict__ beta) {
    int c = threadIdx.x;                   // 128 threads
    float s1 = 0.f, s2 = 0.f;
    for (int i = 0; i < STATS_BLOCKS; i++) {
        s1 += g_p1[i * D + c];
        s2 += g_p2[i * D + c];
    }
    float mu  = s1 / (float)NN;
    float var = s2 / (float)NN - mu * mu;
    float sc  = gamma[c] * rsqrtf(var + BN_EPS);
    g_scale[c] = sc;
    g_shift[c] = beta[c] - mu * sc;
}

// dst = [relu]( scale*h2 + shift )
__global__ void k_norm(float* __restrict__ dst, int relu) {
    int idx = blockIdx.x * blockDim.x + threadIdx.x;   // over NN*32
    if (idx >= NN * 32) return;
    int c4 = (idx & 31) * 4;
    float4 v  = *(const float4*)&g_h2[idx * 4];
    float4 sc = *(const float4*)&g_scale[c4];
    float4 sh = *(const float4*)&g_shift[c4];
    float4 o;
    o.x = sc.x * v.x + sh.x; o.y = sc.y * v.y + sh.y;
    o.z = sc.z * v.z + sh.z; o.w = sc.w * v.w + sh.w;
    if (relu) {
        o.x = fmaxf(o.x, 0.f); o.y = fmaxf(o.y, 0.f);
        o.z = fmaxf(o.z, 0.f); o.w = fmaxf(o.w, 0.f);
    }
    *(float4*)&dst[idx * 4] = o;
}

// ---------------- host ----------------
extern "C" void kernel_launch(void* const* d_in, const int* in_sizes, int n_in,
                              void* d_out, int out_size) {
    const int*   x     = (const int*)d_in[0];
    const int*   ei    = (const int*)d_in[1];
    const int*   ea    = (const int*)d_in[2];
    const float* ae    = (const float*)d_in[3];
    const float* ce    = (const float*)d_in[4];
    const float* he    = (const float*)d_in[5];
    const float* e1    = (const float*)d_in[6];
    const float* e2    = (const float*)d_in[7];
    const float* W1    = (const float*)d_in[8];
    const float* b1    = (const float*)d_in[9];
    const float* W2    = (const float*)d_in[10];
    const float* b2    = (const float*)d_in[11];
    const float* gamma = (const float*)d_in[12];
    const float* beta  = (const float*)d_in[13];
    float* out = (float*)d_out;

    void *p_agg, *p_t, *p_h2, *p_h;
    cudaGetSymbolAddress(&p_agg, g_agg);
    cudaGetSymbolAddress(&p_t,   g_t);
    cudaGetSymbolAddress(&p_h2,  g_h2);
    cudaGetSymbolAddress(&p_h,   g_h);
    float* agg = (float*)p_agg;
    float* t   = (float*)p_t;
    float* h2v = (float*)p_h2;
    float* hv  = (float*)p_h;
    (void)h2v;

    const int vecBlocks  = (NN * 32 + 255) / 256;   // 6250
    const int nodeBlocks = (NN + 255) / 256;        // 196
    const int edgeBlocks = (NE + 255) / 256;        // 2344
    const int aggBlocks  = (NN + 7) / 8;            // 6250
    const int mBlocks    = (NN + 63) / 64;          // 782

    // input node embedding + CSR build (once per launch)
    k_embed<<<vecBlocks, 256>>>(x, ae, ce, he);
    k_zero_deg<<<nodeBlocks, 256>>>();
    k_count<<<edgeBlocks, 256>>>(ei);
    k_scan<<<1, 1024>>>();
    k_cur<<<nodeBlocks, 256>>>();
    k_fill<<<edgeBlocks, 256>>>(ei, ea);

    for (int l = 0; l < NUM_LAYER; l++) {
        k_agg<<<aggBlocks, 256>>>(e1 + (long)l * 6 * D, e2 + (long)l * 4 * D);
        k_gemm<<<dim3(mBlocks, 4), 256>>>(agg, W1 + (long)l * D * 256,
                                          b1 + (long)l * 256, t,
                                          NN, 128, 256, 1);
        k_gemm<<<dim3(mBlocks, 2), 256>>>(t, W2 + (long)l * 256 * D,
                                          b2 + (long)l * D, (float*)p_h2,
                                          NN, 256, 128, 0);
        k_colstats<<<STATS_BLOCKS, 128>>>();
        k_bnfinal<<<1, 128>>>(gamma + (long)l * D, beta + (long)l * D);
        if (l == NUM_LAYER - 1)
            k_norm<<<vecBlocks, 256>>>(out, 0);
        else
            k_norm<<<vecBlocks, 256>>>(hv, 1);
    }
}